// round 16
// baseline (speedup 1.0000x reference)
#include <cuda_runtime.h>
#include <cuda_fp16.h>
#include <cstdint>

#define BB 2
#define SS 2048
#define DD 1024
#define HH 16
#define DHH 64
#define BHH 32
#define MM 4096

// ---------------- scratch ----------------
__device__ float g_Qu[(size_t)BHH * SS * DHH];
__device__ float g_Qv[(size_t)BHH * SS * DHH];
__device__ float g_Kh[(size_t)BHH * SS * DHH];
__device__ float g_VhT[(size_t)BHH * SS * DHH];   // [bh][d][s]
__device__ float g_Ph[(size_t)BHH * SS * DHH];
__device__ __half g_S1h[(size_t)BHH * SS * SS];   // PRE-SHIFTED pos scores (fp16)
__device__ float g_O [(size_t)MM * DD];

// ---------------- fp16 mma helpers ----------------
__device__ __forceinline__ uint32_t h2(float lo, float hi) {
    __half2 h = __floats2half2_rn(lo, hi);
    return *(uint32_t*)&h;
}
__device__ __forceinline__ void mma_f16(float c[4], const uint32_t a[4], const uint32_t b[2]) {
    asm volatile(
        "mma.sync.aligned.m16n8k16.row.col.f32.f16.f16.f32 "
        "{%0,%1,%2,%3}, {%4,%5,%6,%7}, {%8,%9}, {%0,%1,%2,%3};"
        : "+f"(c[0]), "+f"(c[1]), "+f"(c[2]), "+f"(c[3])
        : "r"(a[0]), "r"(a[1]), "r"(a[2]), "r"(a[3]), "r"(b[0]), "r"(b[1]));
}

// ================= fp16 staging (256-thread gemm_core, 128x32 chunks) =================
// A smem: [kstep(2)][mg(8)][lane(32)][4 words]
// B smem (PAIRED): uint2 idx = ((kstep*8 + ngpair)*32 + lane)*2 + (ng&1); ng=0..15
__device__ __forceinline__ void loadA_p(const float* __restrict__ src, int lda,
                                        int kc, int tid, float4* pa) {
#pragma unroll
    for (int j = 0; j < 2; ++j) {
        int i2 = tid + j * 256;
        int c4 = i2 & 7, rr = i2 >> 3;
        int r = ((rr >> 3) << 4) + (rr & 7);
        pa[2 * j]     = *(const float4*)(src + (size_t)r * lda + kc + c4 * 4);
        pa[2 * j + 1] = *(const float4*)(src + (size_t)(r + 8) * lda + kc + c4 * 4);
    }
}
__device__ __forceinline__ void storeA_h(const float4* pa, uint32_t* dst, int tid) {
    uint2* d2 = (uint2*)dst;
#pragma unroll
    for (int j = 0; j < 2; ++j) {
        int i2 = tid + j * 256;
        int c4 = i2 & 7, rr = i2 >> 3;
        int r = ((rr >> 3) << 4) + (rr & 7);
        int kstep = c4 >> 2, cc = c4 & 3, ch = cc >> 1, tigb = (cc & 1) * 2;
        int base = ((kstep * 8 + (r >> 4)) * 32) + (r & 7) * 4 + tigb;
        const float4 lo = pa[2 * j], hi = pa[2 * j + 1];
        uint2 w0, w1;
        w0.x = h2(lo.x, lo.y); w0.y = h2(hi.x, hi.y);
        w1.x = h2(lo.z, lo.w); w1.y = h2(hi.z, hi.w);
        d2[base * 2 + ch]       = w0;
        d2[(base + 1) * 2 + ch] = w1;
    }
}
__device__ __forceinline__ void loadB_h(const float* __restrict__ src, int ldb,
                                        int kc, int tid, float4* pb) {
#pragma unroll
    for (int j = 0; j < 2; ++j) {
        int p = tid + j * 256;
        int r = p >> 2, sub = p & 3;
        int kb = kc + (sub >> 1) * 16 + (sub & 1) * 4;
        pb[2 * j]     = *(const float4*)(src + (size_t)r * ldb + kb);
        pb[2 * j + 1] = *(const float4*)(src + (size_t)r * ldb + kb + 8);
    }
}
__device__ __forceinline__ void storeB_h(const float4* pb, uint32_t* dst, int tid) {
    uint2* d2 = (uint2*)dst;
#pragma unroll
    for (int j = 0; j < 2; ++j) {
        int p = tid + j * 256;
        int r = p >> 2, sub = p & 3;
        int kstep = sub >> 1, q = sub & 1;
        int ng = r >> 3, lanew = (r & 7) * 4 + q * 2;
        int u2base = ((kstep * 8 + (ng >> 1)) * 32 + lanew) * 2 + (ng & 1);
        const float4 a = pb[2 * j], b = pb[2 * j + 1];
        uint2 w0, w1;
        w0.x = h2(a.x, a.y); w0.y = h2(b.x, b.y);
        w1.x = h2(a.z, a.w); w1.y = h2(b.z, b.w);
        d2[u2base]     = w0;
        d2[u2base + 2] = w1;
    }
}

// ================= fp16 GEMM mainloop (C[128x128] in registers) =================
__device__ __forceinline__ void gemm_core(const float* __restrict__ A, int lda,
                                          const float* __restrict__ B, int ldb,
                                          int K, char* sm, float acc[2][8][4]) {
    const int tid  = threadIdx.x;
    const int wid  = tid >> 5;
    const int lane = tid & 31;
    const int mgb  = (wid & 3) * 2;
    const int wn   = wid >> 2;

    uint32_t* s = (uint32_t*)sm;
#pragma unroll
    for (int i = 0; i < 2; ++i)
#pragma unroll
        for (int j = 0; j < 8; ++j)
#pragma unroll
            for (int e = 0; e < 4; ++e) acc[i][j][e] = 0.0f;

    const int nch = K >> 5;
    {
        float4 pa[4], pb[4];
        loadA_p(A, lda, 0, tid, pa);
        loadB_h(B, ldb, 0, tid, pb);
        storeA_h(pa, s, tid);
        storeB_h(pb, s + 2048, tid);
    }
    __syncthreads();

    for (int c = 0; c < nch; ++c) {
        float4 pa[4], pb[4];
        const bool more = (c + 1 < nch);
        if (more) {
            loadA_p(A, lda, (c + 1) * 32, tid, pa);
            loadB_h(B, ldb, (c + 1) * 32, tid, pb);
        }
        uint32_t* As = s + (c & 1) * 4096;
        uint32_t* Bs = As + 2048;
#pragma unroll
        for (int ks = 0; ks < 2; ++ks) {
            uint32_t af[2][4];
#pragma unroll
            for (int mf = 0; mf < 2; ++mf)
                *(uint4*)af[mf] = *(const uint4*)&As[((ks * 8 + mgb + mf) * 32 + lane) * 4];
            uint32_t bf[8][2];
#pragma unroll
            for (int pr = 0; pr < 4; ++pr) {
                uint4 bq = *(const uint4*)&Bs[((ks * 8 + wn * 4 + pr) * 32 + lane) * 4];
                bf[2 * pr][0] = bq.x; bf[2 * pr][1] = bq.y;
                bf[2 * pr + 1][0] = bq.z; bf[2 * pr + 1][1] = bq.w;
            }
#pragma unroll
            for (int mf = 0; mf < 2; ++mf)
#pragma unroll
                for (int nf = 0; nf < 8; ++nf)
                    mma_f16(acc[mf][nf], af[mf], bf[nf]);
        }
        if (more) {
            uint32_t* d = s + ((c + 1) & 1) * 4096;
            storeA_h(pa, d, tid);
            storeB_h(pb, d + 2048, tid);
        }
        __syncthreads();
    }
}

// normal staging: smem float [128][132]
__device__ __forceinline__ void stage_normal(float acc[2][8][4], char* sm) {
    float* smf = (float*)sm;
    const int tid = threadIdx.x, wid = tid >> 5, lane = tid & 31;
    const int gr = lane >> 2, gc = (lane & 3) * 2;
    const int wm = wid & 3, wn = wid >> 2;
#pragma unroll
    for (int mf = 0; mf < 2; ++mf) {
#pragma unroll
        for (int nf = 0; nf < 8; ++nf) {
            int row = wm * 32 + mf * 16 + gr;
            int col = wn * 64 + nf * 8 + gc;
            *(float2*)(smf + row * 132 + col)       = make_float2(acc[mf][nf][0], acc[mf][nf][1]);
            *(float2*)(smf + (row + 8) * 132 + col) = make_float2(acc[mf][nf][2], acc[mf][nf][3]);
        }
    }
    __syncthreads();
}

// transposed staging (for V^T), bias added in regs
__device__ __forceinline__ void stage_transposed(float acc[2][8][4], char* sm,
                                                 const float* __restrict__ bias, int n0) {
    float* smf = (float*)sm;
    const int tid = threadIdx.x, wid = tid >> 5, lane = tid & 31;
    const int gr = lane >> 2, gc = (lane & 3) * 2;
    const int wm = wid & 3, wn = wid >> 2;
#pragma unroll
    for (int nf = 0; nf < 8; ++nf) {
        const int cc = wn * 64 + nf * 8 + gc;
        float2 b2 = *(const float2*)(bias + n0 + cc);
#pragma unroll
        for (int mf = 0; mf < 2; ++mf) {
            const int row0 = wm * 32 + mf * 16 + gr;
            smf[cc * 132 + row0]           = acc[mf][nf][0] + b2.x;
            smf[(cc + 1) * 132 + row0]     = acc[mf][nf][1] + b2.y;
            smf[cc * 132 + row0 + 8]       = acc[mf][nf][2] + b2.x;
            smf[(cc + 1) * 132 + row0 + 8] = acc[mf][nf][3] + b2.y;
        }
    }
    __syncthreads();
}

// ---------------- stage 1: all 4 projections in one launch (z = mode) ----------------
__global__ __launch_bounds__(256) void k_projAll(
    const float* __restrict__ q,  const float* __restrict__ kk, const float* __restrict__ vv,
    const float* __restrict__ pe,
    const float* __restrict__ Wq, const float* __restrict__ bq,
    const float* __restrict__ Wk, const float* __restrict__ bk,
    const float* __restrict__ Wv, const float* __restrict__ bv,
    const float* __restrict__ Wp,
    const float* __restrict__ ub, const float* __restrict__ vb)
{
    extern __shared__ char sm[];
    const int mode = blockIdx.z;
    const float* A; const float* W; const float* bias = nullptr;
    switch (mode) {
        case 0: A = q;  W = Wq; bias = bq; break;
        case 1: A = kk; W = Wk; bias = bk; break;
        case 2: A = vv; W = Wv; bias = bv; break;
        default: A = pe; W = Wp; break;
    }
    const int n0 = blockIdx.x * 128, m0 = blockIdx.y * 128;
    float acc[2][8][4];
    gemm_core(A + (size_t)m0 * DD, DD, W + (size_t)n0 * DD, DD, DD, sm, acc);

    const int tid = threadIdx.x, wid = tid >> 5, lid = tid & 31;

    if (mode == 2) {
        stage_transposed(acc, sm, bias, n0);
        float* smf = (float*)sm;
        const int b = m0 >> 11, s0 = m0 & (SS - 1);
#pragma unroll
        for (int j = 0; j < 16; ++j) {
            const int c_loc = wid * 16 + j;
            const int n = n0 + c_loc;
            const int h = n >> 6, d = n & 63;
            float4 v = *(float4*)(smf + c_loc * 132 + lid * 4);
            *(float4*)(g_VhT + (((size_t)(b * HH + h)) * DHH + d) * SS + s0 + lid * 4) = v;
        }
        return;
    }

    stage_normal(acc, sm);
    float* smf = (float*)sm;
    const int col4 = lid * 4;
    const int n = n0 + col4;
    const int h = n >> 6;
    const int d = n & 63;
    float4 bb = bias ? *(const float4*)(bias + n) : make_float4(0, 0, 0, 0);
    float4 uu = (mode == 0) ? *(const float4*)(ub + n) : make_float4(0, 0, 0, 0);
    float4 vvb = (mode == 0) ? *(const float4*)(vb + n) : make_float4(0, 0, 0, 0);
#pragma unroll
    for (int it = 0; it < 16; ++it) {
        int r = wid * 16 + it;
        float4 v = *(float4*)(smf + r * 132 + col4);
        v.x += bb.x; v.y += bb.y; v.z += bb.z; v.w += bb.w;
        int m = m0 + r, b = m >> 11, ss = m & (SS - 1);
        size_t o = (((size_t)(b * HH + h)) * SS + ss) * DHH + d;
        if (mode == 0) {
            *(float4*)(g_Qu + o) = make_float4(v.x + uu.x, v.y + uu.y, v.z + uu.z, v.w + uu.w);
            *(float4*)(g_Qv + o) = make_float4(v.x + vvb.x, v.y + vvb.y, v.z + vvb.z, v.w + vvb.w);
        } else if (mode == 1) *(float4*)(g_Kh + o) = v;
        else                  *(float4*)(g_Ph + o) = v;
    }
}

// ---------------- zero the rel-shift diagonal k = q+1 ----------------
__global__ void k_zdiag() {
    int i = blockIdx.x * 256 + threadIdx.x;
    if (i >= BHH * (SS - 1)) return;
    int bh = i / (SS - 1), qq = i % (SS - 1);
    g_S1h[(size_t)bh * SS * SS + (size_t)qq * SS + qq + 1] = __float2half(0.0f);
}

// ---------------- stage 2a: pos scores -> PRE-SHIFTED fp16 g_S1h ----------------
__global__ __launch_bounds__(256) void k_pos() {
    extern __shared__ char sm[];
    const int bh = blockIdx.z, k0 = blockIdx.x * 128, q0 = blockIdx.y * 128;
    float acc[2][8][4];
    gemm_core(g_Qv + ((size_t)bh * SS + q0) * DHH, DHH,
              g_Ph + ((size_t)bh * SS + k0) * DHH, DHH, DHH, sm, acc);
    stage_normal(acc, sm);
    float* smf = (float*)sm;
    const int tid = threadIdx.x, wid = tid >> 5, lane = tid & 31;
    __half* S1s = g_S1h + (size_t)bh * SS * SS;
#pragma unroll
    for (int it = 0; it < 16; ++it) {
        const int r = wid * 16 + it;
        const int qq = q0 + r;
        const int boundary = SS - 1 - qq;
#pragma unroll
        for (int c = 0; c < 4; ++c) {
            const int jl = c * 32 + lane;
            const int j  = k0 + jl;
            const __half v = __float2half(smf[r * 132 + jl]);
            if (j >= boundary)
                S1s[(size_t)qq * SS + (j - boundary)] = v;
            else if (qq >= 1)
                S1s[(size_t)(qq - 1) * SS + (j + qq + 1)] = v;
        }
    }
}

// ================= fused flash attention (fp16, paired B frags, dbl-buffered K/V) =====
// 512 threads, q-tile 128, BK 64, 2 syncs/iter.
// Smem words: QuA[4096] | K[2x2048] | V[2x2048] | P[4096] | rs[256] = 16640 (66.5 KB)
#define F2_QUA   0
#define F2_KHB   4096
#define F2_VB    8192
#define F2_PST   12288
#define F2_RS    16384
#define F2_WORDS 16640

__global__ __launch_bounds__(512, 2) void k_flash2() {
    extern __shared__ char sm[];
    uint32_t* s = (uint32_t*)sm;
    const int tid  = threadIdx.x;
    const int wid  = tid >> 5;
    const int lane = tid & 31;
    const int gr   = lane >> 2;
    const int gc   = (lane & 3) * 2;
    const int wm   = wid & 7;
    const int wn   = wid >> 3;

    const int bh = blockIdx.y, q0 = blockIdx.x * 128;
    const int b = bh >> 4, h = bh & (HH - 1);

    const float* Qbase = g_Qu + ((size_t)bh * SS + q0) * DHH;
    const float* Kbase = g_Kh + (size_t)bh * SS * DHH;
    const float* Vbase = g_VhT + (size_t)bh * DHH * SS;
    const __half* S1b  = g_S1h + (size_t)bh * SS * SS;
    const float scale = 0.03125f;

    // stage Qu A-fragments for K=64 (4 ksteps), paired STS.64
    {
        uint2* d2q = (uint2*)(s + F2_QUA);
#pragma unroll
        for (int j = 0; j < 2; ++j) {
            int i2 = tid + j * 512;
            int c4 = i2 & 15, rr = i2 >> 4;
            int r = ((rr >> 3) << 4) + (rr & 7);
            int kstep = c4 >> 2, cc = c4 & 3, ch = cc >> 1, tigb = (cc & 1) * 2;
            float4 lo = *(const float4*)(Qbase + (size_t)r * DHH + c4 * 4);
            float4 hi = *(const float4*)(Qbase + (size_t)(r + 8) * DHH + c4 * 4);
            int base = ((kstep * 8 + (r >> 4)) * 32) + (r & 7) * 4 + tigb;
            uint2 w0, w1;
            w0.x = h2(lo.x, lo.y); w0.y = h2(hi.x, hi.y);
            w1.x = h2(lo.z, lo.w); w1.y = h2(hi.z, hi.w);
            d2q[base * 2 + ch]       = w0;
            d2q[(base + 1) * 2 + ch] = w1;
        }
    }

    float Oacc[4][4];
#pragma unroll
    for (int nf = 0; nf < 4; ++nf)
#pragma unroll
        for (int e = 0; e < 4; ++e) Oacc[nf][e] = 0.0f;
    float rsum[2] = {0.0f, 0.0f};

    // staging coords (paired B layout, NGH=4): ng = n>>3, lanew = (n&7)*4 + q*2
    const int st_n  = tid >> 3;
    const int st_sub = tid & 7;
    const int st_ks = st_sub >> 1, st_q = st_sub & 1;
    const int st_kc = st_ks * 16 + st_q * 4;
    const int st_u2 = ((st_ks * 4 + ((st_n >> 3) >> 1)) * 32 + (st_n & 7) * 4 + st_q * 2) * 2
                    + ((st_n >> 3) & 1);

    const int qg0 = q0 + wm * 16 + gr;
    const int qg1 = qg0 + 8;

    for (int t = 0; t < 32; ++t) {
        const int k0 = t * 64;
        const int buf = (t & 1) * 2048;
        // ---- stage K/V tile into buf (no preceding sync; buffer is free) ----
        {
            const float* src = Kbase + (size_t)(k0 + st_n) * DHH + st_kc;
            float4 a = *(const float4*)(src);
            float4 c = *(const float4*)(src + 8);
            uint2* d2 = (uint2*)(s + F2_KHB + buf);
            uint2 w0, w1;
            w0.x = h2(a.x, a.y); w0.y = h2(c.x, c.y);
            w1.x = h2(a.z, a.w); w1.y = h2(c.z, c.w);
            d2[st_u2]     = w0;
            d2[st_u2 + 2] = w1;
        }
        {
            const float* src = Vbase + (size_t)st_n * SS + k0 + st_kc;
            float4 a = *(const float4*)(src);
            float4 c = *(const float4*)(src + 8);
            uint2* d2 = (uint2*)(s + F2_VB + buf);
            uint2 w0, w1;
            w0.x = h2(a.x, a.y); w0.y = h2(c.x, c.y);
            w1.x = h2(a.z, a.w); w1.y = h2(c.z, c.w);
            d2[st_u2]     = w0;
            d2[st_u2 + 2] = w1;
        }
        __syncthreads();   // sync1: K/V(t) visible (also Q on t=0); P free to overwrite

        // ---- score MMA (paired B loads) ----
        float acc[4][4];
#pragma unroll
        for (int nf = 0; nf < 4; ++nf)
#pragma unroll
            for (int e = 0; e < 4; ++e) acc[nf][e] = 0.0f;
#pragma unroll
        for (int ks = 0; ks < 4; ++ks) {
            uint32_t af[4];
            *(uint4*)af = *(const uint4*)&s[F2_QUA + ((ks * 8 + wm) * 32 + lane) * 4];
#pragma unroll
            for (int pr = 0; pr < 2; ++pr) {
                uint4 bq = *(const uint4*)&s[F2_KHB + buf + ((ks * 4 + wn * 2 + pr) * 32 + lane) * 4];
                uint32_t b0[2] = {bq.x, bq.y};
                uint32_t b1[2] = {bq.z, bq.w};
                mma_f16(acc[2 * pr],     af, b0);
                mma_f16(acc[2 * pr + 1], af, b1);
            }
        }

        // ---- pos add, scale, exp, rowsum; P -> A-frags (1 STS.64/nf) ----
        {
            const __half2* pr0 = (const __half2*)(S1b + (size_t)qg0 * SS + k0 + wn * 32 + gc);
            const __half2* pr1 = (const __half2*)(S1b + (size_t)qg1 * SS + k0 + wn * 32 + gc);
            uint2* pd = (uint2*)(s + F2_PST);
#pragma unroll
            for (int nf = 0; nf < 4; ++nf) {
                const float2 a2 = __half22float2(pr0[nf * 4]);
                const float2 b2 = __half22float2(pr1[nf * 4]);
                float p00 = __expf((acc[nf][0] + a2.x) * scale);
                float p01 = __expf((acc[nf][1] + a2.y) * scale);
                float p10 = __expf((acc[nf][2] + b2.x) * scale);
                float p11 = __expf((acc[nf][3] + b2.y) * scale);
                rsum[0] += p00 + p01;
                rsum[1] += p10 + p11;
                const int kstep = wn * 2 + (nf >> 1);
                const int ch = nf & 1;
                uint2 w;
                w.x = h2(p00, p01);
                w.y = h2(p10, p11);
                pd[(((kstep * 8 + wm) * 32) + gr * 4 + (lane & 3)) * 2 + ch] = w;
            }
        }
        __syncthreads();   // sync2: P visible

        // ---- PV MMA (paired B loads from V) ----
#pragma unroll
        for (int ks = 0; ks < 4; ++ks) {
            uint32_t af[4];
            *(uint4*)af = *(const uint4*)&s[F2_PST + ((ks * 8 + wm) * 32 + lane) * 4];
#pragma unroll
            for (int pr = 0; pr < 2; ++pr) {
                uint4 bq = *(const uint4*)&s[F2_VB + buf + ((ks * 4 + wn * 2 + pr) * 32 + lane) * 4];
                uint32_t b0[2] = {bq.x, bq.y};
                uint32_t b1[2] = {bq.z, bq.w};
                mma_f16(Oacc[2 * pr],     af, b0);
                mma_f16(Oacc[2 * pr + 1], af, b1);
            }
        }
    }
    __syncthreads();

    // ---- reduce rowsums ----
    float* rs = (float*)(s + F2_RS);
#pragma unroll
    for (int half = 0; half < 2; ++half) {
        float v = rsum[half];
        v += __shfl_xor_sync(0xFFFFFFFF, v, 1);
        v += __shfl_xor_sync(0xFFFFFFFF, v, 2);
        if ((lane & 3) == 0)
            rs[wn * 128 + wm * 16 + gr + half * 8] = v;
    }
    __syncthreads();

    // ---- finalize: O / l -> smem staging [128][68] at offset 0 ----
    {
        const int r0 = wm * 16 + gr, r1 = r0 + 8;
        const float i0 = 1.0f / (rs[r0] + rs[128 + r0]);
        const float i1 = 1.0f / (rs[r1] + rs[128 + r1]);
        __syncthreads();
        float* smfO = (float*)s;
#pragma unroll
        for (int nf = 0; nf < 4; ++nf) {
            const int c = wn * 32 + nf * 8 + gc;
            *(float2*)(smfO + r0 * 68 + c) = make_float2(Oacc[nf][0] * i0, Oacc[nf][1] * i0);
            *(float2*)(smfO + r1 * 68 + c) = make_float2(Oacc[nf][2] * i1, Oacc[nf][3] * i1);
        }
        __syncthreads();
#pragma unroll
        for (int it = 0; it < 4; ++it) {
            int idx = tid + it * 512;
            int r = idx >> 4, c4f = (idx & 15) * 4;
            float4 v = *(float4*)(smfO + r * 68 + c4f);
            *(float4*)(g_O + ((size_t)b * SS + q0 + r) * DD + h * 64 + c4f) = v;
        }
    }
}

// ---------------- stage 5: output projection ----------------
__global__ __launch_bounds__(256) void k_outproj(
    const float* __restrict__ Wo, const float* __restrict__ bo, float* __restrict__ out)
{
    extern __shared__ char sm[];
    const int n0 = blockIdx.x * 128, m0 = blockIdx.y * 128;
    float acc[2][8][4];
    gemm_core(g_O + (size_t)m0 * DD, DD, Wo + (size_t)n0 * DD, DD, DD, sm, acc);
    stage_normal(acc, sm);
    float* smf = (float*)sm;
    const int tid = threadIdx.x, wid = tid >> 5, lid = tid & 31;
    float4 bb = *(const float4*)(bo + n0 + lid * 4);
#pragma unroll
    for (int it = 0; it < 16; ++it) {
        int r = wid * 16 + it;
        float4 v = *(float4*)(smf + r * 132 + lid * 4);
        v.x += bb.x; v.y += bb.y; v.z += bb.z; v.w += bb.w;
        *(float4*)(out + (size_t)(m0 + r) * DD + n0 + lid * 4) = v;
    }
}

// ---------------- launch ----------------
extern "C" void kernel_launch(void* const* d_in, const int* in_sizes, int n_in,
                              void* d_out, int out_size)
{
    const float* q  = (const float*)d_in[0];
    const float* k  = (const float*)d_in[1];
    const float* v  = (const float*)d_in[2];
    const float* pe = (const float*)d_in[3];
    const float* Wq = (const float*)d_in[4];
    const float* bq = (const float*)d_in[5];
    const float* Wk = (const float*)d_in[6];
    const float* bk = (const float*)d_in[7];
    const float* Wv = (const float*)d_in[8];
    const float* bv = (const float*)d_in[9];
    const float* Wp = (const float*)d_in[10];
    const float* ub = (const float*)d_in[11];
    const float* vb = (const float*)d_in[12];
    const float* Wo = (const float*)d_in[13];
    const float* bo = (const float*)d_in[14];
    float* out = (float*)d_out;

    const int S128   = 67584;                 // staging [128][132] floats
    const int SFLASH = F2_WORDS * 4;          // 66560 bytes
    cudaFuncSetAttribute(k_projAll, cudaFuncAttributeMaxDynamicSharedMemorySize, S128);
    cudaFuncSetAttribute(k_pos,     cudaFuncAttributeMaxDynamicSharedMemorySize, S128);
    cudaFuncSetAttribute(k_outproj, cudaFuncAttributeMaxDynamicSharedMemorySize, S128);
    cudaFuncSetAttribute(k_flash2,  cudaFuncAttributeMaxDynamicSharedMemorySize, SFLASH);

    k_projAll<<<dim3(DD / 128, MM / 128, 4), 256, S128>>>(
        q, k, v, pe, Wq, bq, Wk, bk, Wv, bv, Wp, ub, vb);

    k_zdiag<<<(BHH * (SS - 1) + 255) / 256, 256>>>();

    k_pos<<<dim3(SS / 128, SS / 128, BHH), 256, S128>>>();

    k_flash2<<<dim3(SS / 128, BHH), 512, SFLASH>>>();

    k_outproj<<<dim3(DD / 128, MM / 128), 256, S128>>>(Wo, bo, out);
}